// round 10
// baseline (speedup 1.0000x reference)
#include <cuda_runtime.h>
#include <math.h>

#define C_CLASSES 10000
#define K_PROTO   4
#define D_DIM     2048
#define N_PROTO   (C_CLASSES * K_PROTO)   // 40000
#define WARPS_PER_BLOCK 8
#define BLOCK1 (WARPS_PER_BLOCK * 32)     // 256
#define GRID1 (N_PROTO / WARPS_PER_BLOCK) // 5000 blocks, one 8-proto tile each

// scratch (no cudaMalloc allowed). g_pmin/g_psum/g_lbl fully overwritten each
// run; g_ticket reset by the last block -> graph-replay deterministic.
__device__ float g_pmin[GRID1];
__device__ float g_psum[GRID1];
__device__ float g_lbl[K_PROTO];
__device__ unsigned int g_ticket = 0;

__global__ __launch_bounds__(BLOCK1) void fused_kernel(
    const float* __restrict__ proto, const float* __restrict__ feat,
    const int* __restrict__ label, float* __restrict__ out) {
    __shared__ float4 sf[D_DIM / 4];      // 8 KB feature tile
    __shared__ float  wdist[WARPS_PER_BLOCK];
    __shared__ bool   amLast;

    const int tid  = threadIdx.x;
    const int lane = tid & 31;
    const int warp = tid >> 5;

    const float4* __restrict__ f4 = reinterpret_cast<const float4*>(feat);
    for (int i = tid; i < D_DIM / 4; i += BLOCK1) sf[i] = f4[i];
    __syncthreads();

    // ---- streaming: one warp per prototype, one tile per block (R4 layout) ----
    const int p = blockIdx.x * WARPS_PER_BLOCK + warp;
    const float4* __restrict__ pp =
        reinterpret_cast<const float4*>(proto + (size_t)p * D_DIM);
    float acc = 0.0f;
#pragma unroll
    for (int i = 0; i < 16; ++i) {        // 16 float4 per lane = 2048/(32*4)
        float4 v = __ldcs(pp + lane + i * 32);   // read-once data
        float4 f = sf[lane + i * 32];
        float dx = v.x - f.x;
        float dy = v.y - f.y;
        float dz = v.z - f.z;
        float dw = v.w - f.w;
        acc += dx * dx + dy * dy + dz * dz + dw * dw;
    }
#pragma unroll
    for (int o = 16; o > 0; o >>= 1)
        acc += __shfl_xor_sync(0xFFFFFFFFu, acc, o);

    if (lane == 0) {
        wdist[warp] = acc;
        if ((p >> 2) == *label) g_lbl[p & 3] = acc;   // label's raw distances
    }
    __syncthreads();

    // ---- block partial (m, s): warp 0 only; release-ticket, no membar ----
    if (tid == 0) {
        float bm = wdist[0];
#pragma unroll
        for (int w = 1; w < WARPS_PER_BLOCK; ++w) bm = fminf(bm, wdist[w]);
        float bs = 0.0f;
#pragma unroll
        for (int w = 0; w < WARPS_PER_BLOCK; ++w) bs += __expf(bm - wdist[w]);
        g_pmin[blockIdx.x] = bm;
        g_psum[blockIdx.x] = bs;
        unsigned int tk;
        asm volatile("atom.add.acq_rel.gpu.u32 %0, [%1], 1;"
                     : "=r"(tk) : "l"(&g_ticket) : "memory");
        amLast = (tk == GRID1 - 1);
    }
    __syncthreads();
    if (!amLast) return;

    // ---- last block: merge 5000 partials, no dependent chain ----
    // pass 1: gmin = min_b m_b
    __shared__ float red[BLOCK1];
    float m = INFINITY;
    for (int i = tid; i < GRID1; i += BLOCK1) m = fminf(m, g_pmin[i]);
    red[tid] = m;
    __syncthreads();
#pragma unroll
    for (int s = BLOCK1 / 2; s > 0; s >>= 1) {
        if (tid < s) red[tid] = fminf(red[tid], red[tid + s]);
        __syncthreads();
    }
    const float gmin = red[0];
    __syncthreads();

    // pass 2: total = sum_b s_b * exp(gmin - m_b)   (independent terms)
    float sum = 0.0f;
    for (int i = tid; i < GRID1; i += BLOCK1)
        sum += g_psum[i] * __expf(gmin - g_pmin[i]);
    red[tid] = sum;
    __syncthreads();
#pragma unroll
    for (int s = BLOCK1 / 2; s > 0; s >>= 1) {
        if (tid < s) red[tid] += red[tid + s];
        __syncthreads();
    }

    if (tid == 0) {
        const float log_one = -gmin + logf(red[0]);
        float prob = 0.0f;
#pragma unroll
        for (int k = 0; k < K_PROTO; ++k)
            prob += log_one + g_lbl[k];   // log_one - logits
        out[0] = prob;
        g_ticket = 0;                      // reset for next graph replay
    }
}

extern "C" void kernel_launch(void* const* d_in, const int* in_sizes, int n_in,
                              void* d_out, int out_size) {
    const float* feature = (const float*)d_in[0];
    const int*   label   = (const int*)d_in[1];
    const float* protos  = (const float*)d_in[2];
    float* out = (float*)d_out;

    fused_kernel<<<GRID1, BLOCK1>>>(protos, feature, label, out);
}

// round 12
// speedup vs baseline: 1.1218x; 1.1218x over previous
#include <cuda_runtime.h>
#include <math.h>

#define C_CLASSES 10000
#define K_PROTO   4
#define D_DIM     2048
#define N_PROTO   (C_CLASSES * K_PROTO)   // 40000
#define WARPS_PER_BLOCK 8
#define BLOCK1 (WARPS_PER_BLOCK * 32)     // 256
#define GRID1 (N_PROTO / WARPS_PER_BLOCK) // 5000
#define BLOCK2 1024

// scratch (no cudaMalloc allowed). All fully overwritten each run before being
// read by kernel 2 — no reset needed, graph-replay deterministic.
__device__ float g_pmin[GRID1];
__device__ float g_psum[GRID1];
__device__ float g_lbl[K_PROTO];

// Kernel 1: one warp per prototype; block emits one (m, s) partial with plain
// stores. No fences/atomics — nothing disturbs the HBM stream. Each block
// triggers PDL completion after issuing its stores.
__global__ __launch_bounds__(BLOCK1) void dist_kernel(
    const float* __restrict__ proto, const float* __restrict__ feat,
    const int* __restrict__ label) {
    __shared__ float4 sf[D_DIM / 4];   // 8 KB feature tile
    __shared__ float  wdist[WARPS_PER_BLOCK];

    const int tid  = threadIdx.x;
    const int lane = tid & 31;
    const int warp = tid >> 5;

    const float4* __restrict__ f4 = reinterpret_cast<const float4*>(feat);
    for (int i = tid; i < D_DIM / 4; i += BLOCK1) sf[i] = f4[i];
    __syncthreads();

    const int p = blockIdx.x * WARPS_PER_BLOCK + warp;
    const float4* __restrict__ pp =
        reinterpret_cast<const float4*>(proto + (size_t)p * D_DIM);
    float acc = 0.0f;
#pragma unroll
    for (int i = 0; i < 16; ++i) {     // 16 float4 per lane = 2048/(32*4)
        float4 v = __ldcs(pp + lane + i * 32);   // read-once data
        float4 f = sf[lane + i * 32];
        float dx = v.x - f.x;
        float dy = v.y - f.y;
        float dz = v.z - f.z;
        float dw = v.w - f.w;
        acc += dx * dx + dy * dy + dz * dz + dw * dw;
    }
#pragma unroll
    for (int o = 16; o > 0; o >>= 1)
        acc += __shfl_xor_sync(0xFFFFFFFFu, acc, o);

    if (lane == 0) {
        wdist[warp] = acc;
        if ((p >> 2) == *label) g_lbl[p & 3] = acc;   // label's raw distances
    }
    __syncthreads();

    // warp 0, lanes 0..7 cooperate on the block partial
    if (warp == 0) {
        float d = (lane < WARPS_PER_BLOCK) ? wdist[lane] : INFINITY;
        float m = d;
#pragma unroll
        for (int o = 4; o > 0; o >>= 1)
            m = fminf(m, __shfl_xor_sync(0xFFu, m, o, 8));
        float e = (lane < WARPS_PER_BLOCK) ? __expf(m - d) : 0.0f;
#pragma unroll
        for (int o = 4; o > 0; o >>= 1)
            e += __shfl_xor_sync(0xFFu, e, o, 8);
        if (lane == 0) {
            g_pmin[blockIdx.x] = m;
            g_psum[blockIdx.x] = e;
        }
#if __CUDA_ARCH__ >= 900
        if (lane == 0) cudaTriggerProgrammaticLaunchCompletion();
#endif
    }
}

// Kernel 2: launched with PDL — resident early, waits for kernel 1's writes,
// then merges 5000 partials with two INDEPENDENT passes (no dependent chain).
__global__ __launch_bounds__(BLOCK2) void merge_kernel(float* __restrict__ out) {
    __shared__ float red[BLOCK2];
    const int tid = threadIdx.x;

#if __CUDA_ARCH__ >= 900
    cudaGridDependencySynchronize();   // primary's writes now visible
#endif

    // pass 1: gmin = min_b m_b  (independent loads)
    float m = INFINITY;
    for (int i = tid; i < GRID1; i += BLOCK2) m = fminf(m, g_pmin[i]);
    red[tid] = m;
    __syncthreads();
#pragma unroll
    for (int s = BLOCK2 / 2; s > 0; s >>= 1) {
        if (tid < s) red[tid] = fminf(red[tid], red[tid + s]);
        __syncthreads();
    }
    const float gmin = red[0];
    __syncthreads();

    // pass 2: total = sum_b s_b * exp(gmin - m_b)  (independent terms)
    float sum = 0.0f;
    for (int i = tid; i < GRID1; i += BLOCK2)
        sum += g_psum[i] * __expf(gmin - g_pmin[i]);
    red[tid] = sum;
    __syncthreads();
#pragma unroll
    for (int s = BLOCK2 / 2; s > 0; s >>= 1) {
        if (tid < s) red[tid] += red[tid + s];
        __syncthreads();
    }

    if (tid == 0) {
        const float log_one = -gmin + logf(red[0]);
        float prob = 0.0f;
#pragma unroll
        for (int k = 0; k < K_PROTO; ++k)
            prob += log_one + g_lbl[k];    // log_one - logits
        out[0] = prob;
    }
}

extern "C" void kernel_launch(void* const* d_in, const int* in_sizes, int n_in,
                              void* d_out, int out_size) {
    const float* feature = (const float*)d_in[0];
    const int*   label   = (const int*)d_in[1];
    const float* protos  = (const float*)d_in[2];
    float* out = (float*)d_out;

    dist_kernel<<<GRID1, BLOCK1>>>(protos, feature, label);

    // PDL launch: merge becomes resident while dist drains, syncs on its writes
    cudaLaunchConfig_t cfg = {};
    cfg.gridDim  = dim3(1, 1, 1);
    cfg.blockDim = dim3(BLOCK2, 1, 1);
    cfg.dynamicSmemBytes = 0;
    cfg.stream = 0;
    cudaLaunchAttribute attr[1];
    attr[0].id = cudaLaunchAttributeProgrammaticStreamSerialization;
    attr[0].val.programmaticStreamSerializationAllowed = 1;
    cfg.attrs = attr;
    cfg.numAttrs = 1;
    cudaLaunchKernelEx(&cfg, merge_kernel, out);
}